// round 15
// baseline (speedup 1.0000x reference)
#include <cuda_runtime.h>
#include <cuda_bf16.h>
#include <cuda_fp16.h>
#include <cstdint>

// Problem constants
#define Bc  8
#define Nn  20000
#define Ec  320000
#define MTOT (Bc * Nn)          // 160000 rows total
#define NBLK 625                // MTOT / 256
#define NTILE (MTOT / 128)      // 1250 GEMM tiles
#define NSM  148
#define LEAKY 0.01f

// Padded bf16 tile: 128 rows x 136 cols (272 B pitch) = 34816 B
#define PITCH_B 272
#define BLOB_B  34816

// Scratch (static device globals — no allocation allowed)
__device__ __half g_xwh[MTOT * 128];   // fp16(xw * dinv_row)  [pre-scaled payload]
__device__ float  g_dinv[MTOT];
__device__ int    g_ideg[MTOT];
__device__ int    g_off [MTOT];
__device__ int    g_cur [MTOT];
__device__ int    g_bsum[NBLK];
__device__ int    g_sorted[Bc * Ec];
// Pre-split W blobs in padded B-layout [n][k]: [matrix][hi/lo][BLOB_B/16]
__device__ uint4  g_wblob[3][2][BLOB_B / 16];

__device__ __forceinline__ float lrelu(float v) {
    return fmaxf(v, 0.0f) + LEAKY * fminf(v, 0.0f);
}
__device__ __forceinline__ uint32_t smem_u32(const void* p) {
    uint32_t a;
    asm("{ .reg .u64 t; cvta.to.shared.u64 t, %1; cvt.u32.u64 %0, t; }"
        : "=r"(a) : "l"(p));
    return a;
}
__device__ __forceinline__ void ldsm_x4(uint32_t addr, uint32_t r[4]) {
    asm volatile("ldmatrix.sync.aligned.m8n8.x4.shared.b16 {%0,%1,%2,%3}, [%4];"
                 : "=r"(r[0]), "=r"(r[1]), "=r"(r[2]), "=r"(r[3]) : "r"(addr));
}
__device__ __forceinline__ void mma16816(float* d, const uint32_t a[4],
                                         uint32_t b0, uint32_t b1) {
    asm volatile("mma.sync.aligned.m16n8k16.row.col.f32.bf16.bf16.f32 "
                 "{%0,%1,%2,%3}, {%4,%5,%6,%7}, {%8,%9}, {%0,%1,%2,%3};"
                 : "+f"(d[0]), "+f"(d[1]), "+f"(d[2]), "+f"(d[3])
                 : "r"(a[0]), "r"(a[1]), "r"(a[2]), "r"(a[3]), "r"(b0), "r"(b1));
}
__device__ __forceinline__ void split2(float v0, float v1, uint32_t& h, uint32_t& l) {
    __nv_bfloat162 hp, lp;
    hp.x = __float2bfloat16(v0); hp.y = __float2bfloat16(v1);
    lp.x = __float2bfloat16(v0 - __bfloat162float(hp.x));
    lp.y = __float2bfloat16(v1 - __bfloat162float(hp.y));
    h = *(uint32_t*)&hp; l = *(uint32_t*)&lp;
}
__device__ __forceinline__ float4 h4_to_f4(uint2 v) {
    float2 a = __half22float2(*(__half2*)&v.x);
    float2 b = __half22float2(*(__half2*)&v.y);
    return make_float4(a.x, a.y, b.x, b.y);
}

// ---------------------------------------------------------------------------
// Edge pipeline: degree -> scan -> reorder (counting sort by dst)
// ---------------------------------------------------------------------------
__global__ void k_init(const float* __restrict__ Wg, const float* __restrict__ W1,
                       const float* __restrict__ W2) {
    int i = blockIdx.x * blockDim.x + threadIdx.x;
    if (i < MTOT) g_ideg[i] = 0;
    if (i < 3 * 8192) {
        int m  = i >> 13;
        int r  = i & 8191;
        int n  = r >> 6;
        int cp = r & 63;
        const float* W = (m == 0) ? Wg : (m == 1) ? W1 : W2;
        float v0 = W[(2 * cp) * 128 + n];     // B[n][2cp] = W[2cp][n]
        float v1 = W[(2 * cp + 1) * 128 + n];
        uint32_t h, l;
        split2(v0, v1, h, l);
        int off = n * PITCH_B + cp * 4;
        *(uint32_t*)((char*)&g_wblob[m][0][0] + off) = h;
        *(uint32_t*)((char*)&g_wblob[m][1][0] + off) = l;
    }
}

__global__ void k_degree(const int* __restrict__ ei) {
    int i = blockIdx.x * blockDim.x + threadIdx.x;
    if (i >= Bc * Ec) return;
    int b = i / Ec;
    int e = i - b * Ec;
    int dst = ei[(size_t)b * 2 * Ec + Ec + e];
    atomicAdd(&g_ideg[b * Nn + dst], 1);
}

__global__ void k_scanA() {
    __shared__ int s[256];
    int i = blockIdx.x * 256 + threadIdx.x;
    int v = g_ideg[i];
    s[threadIdx.x] = v;
    __syncthreads();
#pragma unroll
    for (int d = 1; d < 256; d <<= 1) {
        int t = (threadIdx.x >= d) ? s[threadIdx.x - d] : 0;
        __syncthreads();
        s[threadIdx.x] += t;
        __syncthreads();
    }
    g_off[i] = s[threadIdx.x] - v;
    if (threadIdx.x == 255) g_bsum[blockIdx.x] = s[255];
}

// Merged scanB+scanC: each block computes its own bsum prefix, finalizes
// offsets, cursor copy, and dinv.
__global__ void k_scanC() {
    __shared__ int part[256];
    int acc = 0;
    for (int j = threadIdx.x; j < blockIdx.x; j += 256) acc += g_bsum[j];
    part[threadIdx.x] = acc;
    __syncthreads();
#pragma unroll
    for (int d = 128; d > 0; d >>= 1) {
        if (threadIdx.x < d) part[threadIdx.x] += part[threadIdx.x + d];
        __syncthreads();
    }
    int prefix = part[0];
    int i = blockIdx.x * 256 + threadIdx.x;
    int o = g_off[i] + prefix;
    g_off[i] = o;
    g_cur[i] = o;
    g_dinv[i] = rsqrtf((float)g_ideg[i] + 1.0f);   // +1 self loop
}

__global__ void k_reorder(const int* __restrict__ ei) {
    int i = blockIdx.x * blockDim.x + threadIdx.x;
    if (i >= Bc * Ec) return;
    int b = i / Ec;
    int e = i - b * Ec;
    const int* eb = ei + (size_t)b * 2 * Ec;
    int src = __ldg(&eb[e]);
    int dst = __ldg(&eb[Ec + e]);
    int pos = atomicAdd(&g_cur[b * Nn + dst], 1);
    g_sorted[pos] = b * Nn + src;
}

// ---------------------------------------------------------------------------
// Shared GEMM machinery (HMMA bf16x3 split, fp32 accum)
// ---------------------------------------------------------------------------
struct WarpCoords {
    int m0w, n0w;
    uint32_t a_off, b_off;
};
__device__ __forceinline__ WarpCoords warp_coords(int wid, int lane) {
    WarpCoords w;
    w.m0w = (wid >> 1) * 32;
    w.n0w = (wid & 1) * 64;
    w.a_off = (uint32_t)(w.m0w + (lane & 15)) * PITCH_B + ((lane >> 4) ? 16u : 0u);
    w.b_off = (uint32_t)(w.n0w + (lane & 7) + (lane >> 4) * 8) * PITCH_B
            + (((lane >> 3) & 1) ? 16u : 0u);
    return w;
}

__device__ __forceinline__ void run_mma(float acc[2][8][4],
                                        uint32_t ah, uint32_t al,
                                        uint32_t wh, uint32_t wl,
                                        const WarpCoords& wc) {
    const uint32_t abase[3] = {ah, ah, al};
    const uint32_t bbase[3] = {wh, wl, wh};
#pragma unroll 1
    for (int pass = 0; pass < 3; pass++) {
        uint32_t aaddr = abase[pass] + wc.a_off;
        uint32_t baddr = bbase[pass] + wc.b_off;
#pragma unroll
        for (int k = 0; k < 8; k++) {
            uint32_t af[2][4], bf[4][4];
            ldsm_x4(aaddr + k * 32,                af[0]);
            ldsm_x4(aaddr + k * 32 + 16 * PITCH_B, af[1]);
#pragma unroll
            for (int ng = 0; ng < 4; ng++)
                ldsm_x4(baddr + k * 32 + ng * 16 * PITCH_B, bf[ng]);
#pragma unroll
            for (int mt = 0; mt < 2; mt++)
#pragma unroll
                for (int nt = 0; nt < 8; nt++)
                    mma16816(acc[mt][nt], af[mt],
                             bf[nt >> 1][(nt & 1) * 2], bf[nt >> 1][(nt & 1) * 2 + 1]);
        }
    }
}

// ---------------------------------------------------------------------------
// GEMM1 (persistent): xwh = fp16((concat(nf,act) @ Wg) * dinv_row)
// smem: AH|AL|WH|WL
// ---------------------------------------------------------------------------
#define SMEM1 (4 * BLOB_B)

__global__ __launch_bounds__(256)
void k_tc1(const float* __restrict__ nf, const float* __restrict__ act)
{
    extern __shared__ char smem[];
    const uint32_t sb = smem_u32(smem);
    const int tid  = threadIdx.x;
    const int wid  = tid >> 5;
    const int lane = tid & 31;

    {   // W blobs (once per SM)
        const uint4* wh = &g_wblob[0][0][0];
        const uint4* wl = &g_wblob[0][1][0];
        uint4* sh = (uint4*)(smem + 2 * BLOB_B);
        uint4* sl = (uint4*)(smem + 3 * BLOB_B);
        for (int i = tid; i < BLOB_B / 16; i += 256) { sh[i] = wh[i]; sl[i] = wl[i]; }
    }
    const WarpCoords wc = warp_coords(wid, lane);
    const int gq = lane >> 2;
    const int tq = lane & 3;

    for (int tile = blockIdx.x; tile < NTILE; tile += gridDim.x) {
        const size_t row0 = (size_t)tile * 128;
        {   // A = concat(nf, act)
            int row  = tid >> 1;
            int half = tid & 1;
            size_t rowg = row0 + row;
            const float* srcx = half ? (act + rowg * 64) : (nf + rowg * 64);
            char* ah = smem + row * PITCH_B + half * 128;
            char* al = smem + BLOB_B + row * PITCH_B + half * 128;
#pragma unroll
            for (int q = 0; q < 16; q++) {
                float4 a4 = ((const float4*)srcx)[q];
                uint32_t h, l;
                split2(a4.x, a4.y, h, l);
                *(uint32_t*)(ah + q * 8) = h;  *(uint32_t*)(al + q * 8) = l;
                split2(a4.z, a4.w, h, l);
                *(uint32_t*)(ah + q * 8 + 4) = h;  *(uint32_t*)(al + q * 8 + 4) = l;
            }
        }
        __syncthreads();

        float acc[2][8][4];
#pragma unroll
        for (int mt = 0; mt < 2; mt++)
#pragma unroll
            for (int nt = 0; nt < 8; nt++)
#pragma unroll
                for (int q = 0; q < 4; q++) acc[mt][nt][q] = 0.0f;

        run_mma(acc, sb, sb + BLOB_B, sb + 2 * BLOB_B, sb + 3 * BLOB_B, wc);

#pragma unroll
        for (int mt = 0; mt < 2; mt++) {
            size_t r0 = row0 + wc.m0w + mt * 16 + gq;
            size_t r1 = r0 + 8;
            float d0 = g_dinv[r0], d1 = g_dinv[r1];
#pragma unroll
            for (int nt = 0; nt < 8; nt++) {
                int c = wc.n0w + nt * 8 + tq * 2;
                float* a = acc[mt][nt];
                *(__half2*)(g_xwh + r0 * 128 + c) =
                    __floats2half2_rn(a[0] * d0, a[1] * d0);
                *(__half2*)(g_xwh + r1 * 128 + c) =
                    __floats2half2_rn(a[2] * d1, a[3] * d1);
            }
        }
        __syncthreads();   // all mma reads of A done before next tile's A build
    }
}

// ---------------------------------------------------------------------------
// Fused GEMM2+GEMM3 (persistent) with INLINE aggregation:
//   per warp, 16 rows: conv = dinv*(self + gather-sum from g_xwh)
//   A = relu(conv+bg)+x  -> split into A blobs (no g_conv round-trip)
//   h1 = lrelu(A@W1+b1) -> re-split; out = lrelu(h1@W2+b2) @ W3 + b3
// smem: AH|AL|W1H|W1L|W2H|W2L | b1 | b2 | W3 | red
// ---------------------------------------------------------------------------
#define OFF23_B1  (6 * BLOB_B)
#define OFF23_B2  (6 * BLOB_B + 512)
#define OFF23_W3  (6 * BLOB_B + 1024)
#define OFF23_RED (6 * BLOB_B + 1536)
#define SMEM23    (6 * BLOB_B + 2560)

__global__ __launch_bounds__(256)
void k_tc23(const float* __restrict__ nf, const float* __restrict__ act,
            const float* __restrict__ bg,
            const float* __restrict__ b1, const float* __restrict__ b2,
            const float* __restrict__ W3, const float* __restrict__ b3p,
            float* __restrict__ out)
{
    extern __shared__ char smem[];
    const uint32_t sb = smem_u32(smem);
    const int tid  = threadIdx.x;
    const int wid  = tid >> 5;
    const int lane = tid & 31;

    {   // W1 + W2 blobs + biases (once per SM)
        const uint4* w1h = &g_wblob[1][0][0];
        const uint4* w1l = &g_wblob[1][1][0];
        const uint4* w2h = &g_wblob[2][0][0];
        const uint4* w2l = &g_wblob[2][1][0];
        uint4* s1h = (uint4*)(smem + 2 * BLOB_B);
        uint4* s1l = (uint4*)(smem + 3 * BLOB_B);
        uint4* s2h = (uint4*)(smem + 4 * BLOB_B);
        uint4* s2l = (uint4*)(smem + 5 * BLOB_B);
        for (int i = tid; i < BLOB_B / 16; i += 256) {
            s1h[i] = w1h[i]; s1l[i] = w1l[i];
            s2h[i] = w2h[i]; s2l[i] = w2l[i];
        }
    }
    if (tid < 32)
        ((float4*)(smem + OFF23_B1))[tid] = ((const float4*)b1)[tid];
    else if (tid < 64)
        ((float4*)(smem + OFF23_B2))[tid - 32] = ((const float4*)b2)[tid - 32];
    else if (tid < 96)
        ((float4*)(smem + OFF23_W3))[tid - 64] = ((const float4*)W3)[tid - 64];

    const WarpCoords wc = warp_coords(wid, lane);
    const int gq = lane >> 2;
    const int tq = lane & 3;
    const float b3v = __ldg(b3p);
    // per-lane bg chunk (cols lane*4 .. lane*4+3), hoisted
    const float4 bg4 = __ldg((const float4*)(bg + lane * 4));
    const uint2* xbase = (const uint2*)g_xwh;

    for (int tile = blockIdx.x; tile < NTILE; tile += gridDim.x) {
        const size_t row0 = (size_t)tile * 128;

        // ---- A-build with inline aggregation: warp r-loop over 16 rows ----
        {
            char* ahb = smem;
            char* alb = smem + BLOB_B;
#pragma unroll 1
            for (int r = 0; r < 16; r++) {
                int row = wid * 16 + r;
                size_t node = row0 + row;
                const int off = g_off[node];
                const int deg = g_ideg[node];
                const float dv = g_dinv[node];

                float4 sf = h4_to_f4(xbase[node * 32 + lane]);
                float ax = sf.x, ay = sf.y, az = sf.z, aw = sf.w;

                int e = 0;
                for (; e + 4 <= deg; e += 4) {
                    int s0 = g_sorted[off + e + 0];
                    int s1 = g_sorted[off + e + 1];
                    int s2 = g_sorted[off + e + 2];
                    int s3 = g_sorted[off + e + 3];
                    float4 f0 = h4_to_f4(xbase[(size_t)s0 * 32 + lane]);
                    float4 f1 = h4_to_f4(xbase[(size_t)s1 * 32 + lane]);
                    float4 f2 = h4_to_f4(xbase[(size_t)s2 * 32 + lane]);
                    float4 f3 = h4_to_f4(xbase[(size_t)s3 * 32 + lane]);
                    ax += f0.x + f1.x + f2.x + f3.x;
                    ay += f0.y + f1.y + f2.y + f3.y;
                    az += f0.z + f1.z + f2.z + f3.z;
                    aw += f0.w + f1.w + f2.w + f3.w;
                }
                for (; e < deg; e++) {
                    int s0 = g_sorted[off + e];
                    float4 f0 = h4_to_f4(xbase[(size_t)s0 * 32 + lane]);
                    ax += f0.x; ay += f0.y; az += f0.z; aw += f0.w;
                }

                // x residual: cols lane*4 (lanes 0-15 -> nf, 16-31 -> act)
                const float* xsrc = (lane < 16)
                    ? (nf + node * 64 + lane * 4)
                    : (act + node * 64 + (lane - 16) * 4);
                float4 x4 = *(const float4*)xsrc;

                float v0 = fmaxf(ax * dv + bg4.x, 0.0f) + x4.x;
                float v1 = fmaxf(ay * dv + bg4.y, 0.0f) + x4.y;
                float v2 = fmaxf(az * dv + bg4.z, 0.0f) + x4.z;
                float v3 = fmaxf(aw * dv + bg4.w, 0.0f) + x4.w;

                uint32_t h, l;
                char* ah = ahb + row * PITCH_B + lane * 8;
                char* al = alb + row * PITCH_B + lane * 8;
                split2(v0, v1, h, l);
                *(uint32_t*)ah = h;  *(uint32_t*)al = l;
                split2(v2, v3, h, l);
                *(uint32_t*)(ah + 4) = h;  *(uint32_t*)(al + 4) = l;
            }
        }
        __syncthreads();

        float acc[2][8][4];
#pragma unroll
        for (int mt = 0; mt < 2; mt++)
#pragma unroll
            for (int nt = 0; nt < 8; nt++)
#pragma unroll
                for (int q = 0; q < 4; q++) acc[mt][nt][q] = 0.0f;

        // ---- GEMM2: A @ W1 ----
        run_mma(acc, sb, sb + BLOB_B, sb + 2 * BLOB_B, sb + 3 * BLOB_B, wc);
        __syncthreads();

        // ---- h1 = lrelu(acc + b1) -> re-split into A blobs ----
        {
            const float* b1s = (const float*)(smem + OFF23_B1);
            char* ah = smem;
            char* al = smem + BLOB_B;
#pragma unroll
            for (int mt = 0; mt < 2; mt++) {
                int lr0 = wc.m0w + mt * 16 + gq;
                int lr1 = lr0 + 8;
#pragma unroll
                for (int nt = 0; nt < 8; nt++) {
                    int c = wc.n0w + nt * 8 + tq * 2;
                    float bb0 = b1s[c], bb1 = b1s[c + 1];
                    float* a = acc[mt][nt];
                    uint32_t h, l;
                    split2(lrelu(a[0] + bb0), lrelu(a[1] + bb1), h, l);
                    *(uint32_t*)(ah + lr0 * PITCH_B + c * 2) = h;
                    *(uint32_t*)(al + lr0 * PITCH_B + c * 2) = l;
                    split2(lrelu(a[2] + bb0), lrelu(a[3] + bb1), h, l);
                    *(uint32_t*)(ah + lr1 * PITCH_B + c * 2) = h;
                    *(uint32_t*)(al + lr1 * PITCH_B + c * 2) = l;
                }
            }
        }
        __syncthreads();

        // ---- GEMM3: h1 @ W2 ----
#pragma unroll
        for (int mt = 0; mt < 2; mt++)
#pragma unroll
            for (int nt = 0; nt < 8; nt++)
#pragma unroll
                for (int q = 0; q < 4; q++) acc[mt][nt][q] = 0.0f;
        run_mma(acc, sb, sb + BLOB_B, sb + 4 * BLOB_B, sb + 5 * BLOB_B, wc);

        // ---- head: out = lrelu(acc + b2) . W3 + b3 ----
        {
            const float* b2s = (const float*)(smem + OFF23_B2);
            const float* w3s = (const float*)(smem + OFF23_W3);
            float* red = (float*)(smem + OFF23_RED);   // [128][2]
#pragma unroll
            for (int mt = 0; mt < 2; mt++) {
                float s0 = 0.0f, s1 = 0.0f;
#pragma unroll
                for (int nt = 0; nt < 8; nt++) {
                    int c = wc.n0w + nt * 8 + tq * 2;
                    float bb0 = b2s[c], bb1 = b2s[c + 1];
                    float w0 = w3s[c],  w1 = w3s[c + 1];
                    float* a = acc[mt][nt];
                    s0 = fmaf(lrelu(a[0] + bb0), w0, s0);
                    s0 = fmaf(lrelu(a[1] + bb1), w1, s0);
                    s1 = fmaf(lrelu(a[2] + bb0), w0, s1);
                    s1 = fmaf(lrelu(a[3] + bb1), w1, s1);
                }
                s0 += __shfl_xor_sync(0xffffffffu, s0, 1);
                s0 += __shfl_xor_sync(0xffffffffu, s0, 2);
                s1 += __shfl_xor_sync(0xffffffffu, s1, 1);
                s1 += __shfl_xor_sync(0xffffffffu, s1, 2);
                if (tq == 0) {
                    int lr0 = wc.m0w + mt * 16 + gq;
                    red[lr0 * 2 + (wid & 1)]       = s0;
                    red[(lr0 + 8) * 2 + (wid & 1)] = s1;
                }
            }
            __syncthreads();   // also guards next tile's A-blob overwrite
            if (tid < 128)
                out[row0 + tid] = red[tid * 2] + red[tid * 2 + 1] + b3v;
        }
    }
}

// ---------------------------------------------------------------------------
extern "C" void kernel_launch(void* const* d_in, const int* in_sizes, int n_in,
                              void* d_out, int out_size)
{
    const float* nf  = (const float*)d_in[0];
    const float* act = (const float*)d_in[1];
    const int*   ei  = (const int*)d_in[2];     // JAX x64 disabled -> int32
    const float* Wg  = (const float*)d_in[3];
    const float* bg  = (const float*)d_in[4];
    const float* W1  = (const float*)d_in[5];
    const float* b1  = (const float*)d_in[6];
    const float* W2  = (const float*)d_in[7];
    const float* b2  = (const float*)d_in[8];
    const float* W3  = (const float*)d_in[9];
    const float* b3  = (const float*)d_in[10];
    float* out = (float*)d_out;

    cudaFuncSetAttribute(k_tc1,  cudaFuncAttributeMaxDynamicSharedMemorySize, SMEM1);
    cudaFuncSetAttribute(k_tc23, cudaFuncAttributeMaxDynamicSharedMemorySize, SMEM23);

    // Edge indexing structure (counting sort by dst) + weight prep
    k_init    <<<NBLK, 256>>>(Wg, W1, W2);
    k_degree  <<<(Bc * Ec + 255) / 256, 256>>>(ei);
    k_scanA   <<<NBLK, 256>>>();
    k_scanC   <<<NBLK, 256>>>();     // merged scanB+scanC
    k_reorder <<<(Bc * Ec + 255) / 256, 256>>>(ei);

    // GEMM1 (persistent): xwh = fp16((concat(nf,act) @ Wg) * dinv)
    k_tc1<<<NSM, 256, SMEM1>>>(nf, act);
    // Fused GEMM2+GEMM3 (persistent, inline aggregation + head)
    k_tc23<<<NSM, 256, SMEM23>>>(nf, act, bg, b1, b2, W3, b3, out);
}

// round 16
// speedup vs baseline: 1.5357x; 1.5357x over previous
#include <cuda_runtime.h>
#include <cuda_bf16.h>
#include <cuda_fp16.h>
#include <cstdint>

// Problem constants
#define Bc  8
#define Nn  20000
#define Ec  320000
#define MTOT (Bc * Nn)          // 160000 rows total
#define NBLK 625                // MTOT / 256
#define NTILE (MTOT / 128)      // 1250 GEMM tiles
#define NSM  148
#define LEAKY 0.01f

// Padded bf16 tile: 128 rows x 136 cols (272 B pitch) = 34816 B
#define PITCH_B 272
#define BLOB_B  34816

// Scratch (static device globals — no allocation allowed)
__device__ __half g_xwh [MTOT * 128];   // fp16(xw * dinv_row)  [pre-scaled payload]
__device__ __half g_convh[MTOT * 128];  // fp16 conv (aggregate -> GEMM2 A-build)
__device__ float  g_dinv[MTOT];
__device__ int    g_ideg[MTOT];
__device__ int    g_off [MTOT];
__device__ int    g_cur [MTOT];
__device__ int    g_bsum[NBLK];
__device__ int    g_sorted[Bc * Ec];
// Pre-split W blobs in padded B-layout [n][k]: [matrix][hi/lo][BLOB_B/16]
__device__ uint4  g_wblob[3][2][BLOB_B / 16];

__device__ __forceinline__ float lrelu(float v) {
    return fmaxf(v, 0.0f) + LEAKY * fminf(v, 0.0f);
}
__device__ __forceinline__ uint32_t smem_u32(const void* p) {
    uint32_t a;
    asm("{ .reg .u64 t; cvta.to.shared.u64 t, %1; cvt.u32.u64 %0, t; }"
        : "=r"(a) : "l"(p));
    return a;
}
__device__ __forceinline__ void ldsm_x4(uint32_t addr, uint32_t r[4]) {
    asm volatile("ldmatrix.sync.aligned.m8n8.x4.shared.b16 {%0,%1,%2,%3}, [%4];"
                 : "=r"(r[0]), "=r"(r[1]), "=r"(r[2]), "=r"(r[3]) : "r"(addr));
}
__device__ __forceinline__ void mma16816(float* d, const uint32_t a[4],
                                         uint32_t b0, uint32_t b1) {
    asm volatile("mma.sync.aligned.m16n8k16.row.col.f32.bf16.bf16.f32 "
                 "{%0,%1,%2,%3}, {%4,%5,%6,%7}, {%8,%9}, {%0,%1,%2,%3};"
                 : "+f"(d[0]), "+f"(d[1]), "+f"(d[2]), "+f"(d[3])
                 : "r"(a[0]), "r"(a[1]), "r"(a[2]), "r"(a[3]), "r"(b0), "r"(b1));
}
__device__ __forceinline__ void split2(float v0, float v1, uint32_t& h, uint32_t& l) {
    __nv_bfloat162 hp, lp;
    hp.x = __float2bfloat16(v0); hp.y = __float2bfloat16(v1);
    lp.x = __float2bfloat16(v0 - __bfloat162float(hp.x));
    lp.y = __float2bfloat16(v1 - __bfloat162float(hp.y));
    h = *(uint32_t*)&hp; l = *(uint32_t*)&lp;
}
__device__ __forceinline__ float4 h4_to_f4(uint2 v) {
    float2 a = __half22float2(*(__half2*)&v.x);
    float2 b = __half22float2(*(__half2*)&v.y);
    return make_float4(a.x, a.y, b.x, b.y);
}

// ---------------------------------------------------------------------------
// Edge pipeline: degree -> scan -> reorder (counting sort by dst) -> aggregate
// ---------------------------------------------------------------------------
__global__ void k_init(const float* __restrict__ Wg, const float* __restrict__ W1,
                       const float* __restrict__ W2) {
    int i = blockIdx.x * blockDim.x + threadIdx.x;
    if (i < MTOT) g_ideg[i] = 0;
    if (i < 3 * 8192) {
        int m  = i >> 13;
        int r  = i & 8191;
        int n  = r >> 6;
        int cp = r & 63;
        const float* W = (m == 0) ? Wg : (m == 1) ? W1 : W2;
        float v0 = W[(2 * cp) * 128 + n];     // B[n][2cp] = W[2cp][n]
        float v1 = W[(2 * cp + 1) * 128 + n];
        uint32_t h, l;
        split2(v0, v1, h, l);
        int off = n * PITCH_B + cp * 4;
        *(uint32_t*)((char*)&g_wblob[m][0][0] + off) = h;
        *(uint32_t*)((char*)&g_wblob[m][1][0] + off) = l;
    }
}

__global__ void k_degree(const int* __restrict__ ei) {
    int i = blockIdx.x * blockDim.x + threadIdx.x;
    if (i >= Bc * Ec) return;
    int b = i / Ec;
    int e = i - b * Ec;
    int dst = ei[(size_t)b * 2 * Ec + Ec + e];
    atomicAdd(&g_ideg[b * Nn + dst], 1);
}

__global__ void k_scanA() {
    __shared__ int s[256];
    int i = blockIdx.x * 256 + threadIdx.x;
    int v = g_ideg[i];
    s[threadIdx.x] = v;
    __syncthreads();
#pragma unroll
    for (int d = 1; d < 256; d <<= 1) {
        int t = (threadIdx.x >= d) ? s[threadIdx.x - d] : 0;
        __syncthreads();
        s[threadIdx.x] += t;
        __syncthreads();
    }
    g_off[i] = s[threadIdx.x] - v;
    if (threadIdx.x == 255) g_bsum[blockIdx.x] = s[255];
}

// Merged scanB+scanC: each block computes its own bsum prefix, finalizes
// offsets, cursor copy, and dinv.
__global__ void k_scanC() {
    __shared__ int part[256];
    int acc = 0;
    for (int j = threadIdx.x; j < blockIdx.x; j += 256) acc += g_bsum[j];
    part[threadIdx.x] = acc;
    __syncthreads();
#pragma unroll
    for (int d = 128; d > 0; d >>= 1) {
        if (threadIdx.x < d) part[threadIdx.x] += part[threadIdx.x + d];
        __syncthreads();
    }
    int prefix = part[0];
    int i = blockIdx.x * 256 + threadIdx.x;
    int o = g_off[i] + prefix;
    g_off[i] = o;
    g_cur[i] = o;
    g_dinv[i] = rsqrtf((float)g_ideg[i] + 1.0f);   // +1 self loop
}

__global__ void k_reorder(const int* __restrict__ ei) {
    int i = blockIdx.x * blockDim.x + threadIdx.x;
    if (i >= Bc * Ec) return;
    int b = i / Ec;
    int e = i - b * Ec;
    const int* eb = ei + (size_t)b * 2 * Ec;
    int src = __ldg(&eb[e]);
    int dst = __ldg(&eb[Ec + e]);
    int pos = atomicAdd(&g_cur[b * Nn + dst], 1);
    g_sorted[pos] = b * Nn + src;
}

// One warp per node (64 warps/SM — latency-hiding occupancy):
// conv[i] = dinv[i] * ( xwh'[i] + sum_e xwh'[src] ), written fp16.
__global__ void k_aggregate() {
    int gw   = (blockIdx.x * blockDim.x + threadIdx.x) >> 5;
    int lane = threadIdx.x & 31;
    if (gw >= MTOT) return;
    const int off = g_off[gw];
    const int deg = g_ideg[gw];
    const float dv = g_dinv[gw];

    const uint2* base = (const uint2*)g_xwh;   // 8B = 4 halves per lane
    float4 sf = h4_to_f4(base[(size_t)gw * 32 + lane]);
    float ax = sf.x, ay = sf.y, az = sf.z, aw = sf.w;   // raw self payload

    int e = 0;
    for (; e + 4 <= deg; e += 4) {
        int s0 = g_sorted[off + e + 0];
        int s1 = g_sorted[off + e + 1];
        int s2 = g_sorted[off + e + 2];
        int s3 = g_sorted[off + e + 3];
        float4 f0 = h4_to_f4(base[(size_t)s0 * 32 + lane]);
        float4 f1 = h4_to_f4(base[(size_t)s1 * 32 + lane]);
        float4 f2 = h4_to_f4(base[(size_t)s2 * 32 + lane]);
        float4 f3 = h4_to_f4(base[(size_t)s3 * 32 + lane]);
        ax += f0.x + f1.x + f2.x + f3.x;
        ay += f0.y + f1.y + f2.y + f3.y;
        az += f0.z + f1.z + f2.z + f3.z;
        aw += f0.w + f1.w + f2.w + f3.w;
    }
    for (; e < deg; e++) {
        int s0 = g_sorted[off + e];
        float4 f0 = h4_to_f4(base[(size_t)s0 * 32 + lane]);
        ax += f0.x; ay += f0.y; az += f0.z; aw += f0.w;
    }
    uint2 outp;
    *(__half2*)&outp.x = __floats2half2_rn(ax * dv, ay * dv);
    *(__half2*)&outp.y = __floats2half2_rn(az * dv, aw * dv);
    ((uint2*)g_convh)[(size_t)gw * 32 + lane] = outp;
}

// ---------------------------------------------------------------------------
// Shared GEMM machinery (HMMA bf16x3 split, fp32 accum)
// ---------------------------------------------------------------------------
struct WarpCoords {
    int m0w, n0w;
    uint32_t a_off, b_off;
};
__device__ __forceinline__ WarpCoords warp_coords(int wid, int lane) {
    WarpCoords w;
    w.m0w = (wid >> 1) * 32;
    w.n0w = (wid & 1) * 64;
    w.a_off = (uint32_t)(w.m0w + (lane & 15)) * PITCH_B + ((lane >> 4) ? 16u : 0u);
    w.b_off = (uint32_t)(w.n0w + (lane & 7) + (lane >> 4) * 8) * PITCH_B
            + (((lane >> 3) & 1) ? 16u : 0u);
    return w;
}

__device__ __forceinline__ void run_mma(float acc[2][8][4],
                                        uint32_t ah, uint32_t al,
                                        uint32_t wh, uint32_t wl,
                                        const WarpCoords& wc) {
    const uint32_t abase[3] = {ah, ah, al};
    const uint32_t bbase[3] = {wh, wl, wh};
#pragma unroll 1
    for (int pass = 0; pass < 3; pass++) {
        uint32_t aaddr = abase[pass] + wc.a_off;
        uint32_t baddr = bbase[pass] + wc.b_off;
#pragma unroll
        for (int k = 0; k < 8; k++) {
            uint32_t af[2][4], bf[4][4];
            ldsm_x4(aaddr + k * 32,                af[0]);
            ldsm_x4(aaddr + k * 32 + 16 * PITCH_B, af[1]);
#pragma unroll
            for (int ng = 0; ng < 4; ng++)
                ldsm_x4(baddr + k * 32 + ng * 16 * PITCH_B, bf[ng]);
#pragma unroll
            for (int mt = 0; mt < 2; mt++)
#pragma unroll
                for (int nt = 0; nt < 8; nt++)
                    mma16816(acc[mt][nt], af[mt],
                             bf[nt >> 1][(nt & 1) * 2], bf[nt >> 1][(nt & 1) * 2 + 1]);
        }
    }
}

// ---------------------------------------------------------------------------
// GEMM1 (persistent): xwh = fp16((concat(nf,act) @ Wg) * dinv_row)
// smem: AH|AL|WH|WL
// ---------------------------------------------------------------------------
#define SMEM1 (4 * BLOB_B)

__global__ __launch_bounds__(256)
void k_tc1(const float* __restrict__ nf, const float* __restrict__ act)
{
    extern __shared__ char smem[];
    const uint32_t sb = smem_u32(smem);
    const int tid  = threadIdx.x;
    const int wid  = tid >> 5;
    const int lane = tid & 31;

    {   // W blobs (once per SM)
        const uint4* wh = &g_wblob[0][0][0];
        const uint4* wl = &g_wblob[0][1][0];
        uint4* sh = (uint4*)(smem + 2 * BLOB_B);
        uint4* sl = (uint4*)(smem + 3 * BLOB_B);
        for (int i = tid; i < BLOB_B / 16; i += 256) { sh[i] = wh[i]; sl[i] = wl[i]; }
    }
    const WarpCoords wc = warp_coords(wid, lane);
    const int gq = lane >> 2;
    const int tq = lane & 3;

    for (int tile = blockIdx.x; tile < NTILE; tile += gridDim.x) {
        const size_t row0 = (size_t)tile * 128;
        {   // A = concat(nf, act)
            int row  = tid >> 1;
            int half = tid & 1;
            size_t rowg = row0 + row;
            const float* srcx = half ? (act + rowg * 64) : (nf + rowg * 64);
            char* ah = smem + row * PITCH_B + half * 128;
            char* al = smem + BLOB_B + row * PITCH_B + half * 128;
#pragma unroll
            for (int q = 0; q < 16; q++) {
                float4 a4 = ((const float4*)srcx)[q];
                uint32_t h, l;
                split2(a4.x, a4.y, h, l);
                *(uint32_t*)(ah + q * 8) = h;  *(uint32_t*)(al + q * 8) = l;
                split2(a4.z, a4.w, h, l);
                *(uint32_t*)(ah + q * 8 + 4) = h;  *(uint32_t*)(al + q * 8 + 4) = l;
            }
        }
        __syncthreads();

        float acc[2][8][4];
#pragma unroll
        for (int mt = 0; mt < 2; mt++)
#pragma unroll
            for (int nt = 0; nt < 8; nt++)
#pragma unroll
                for (int q = 0; q < 4; q++) acc[mt][nt][q] = 0.0f;

        run_mma(acc, sb, sb + BLOB_B, sb + 2 * BLOB_B, sb + 3 * BLOB_B, wc);

#pragma unroll
        for (int mt = 0; mt < 2; mt++) {
            size_t r0 = row0 + wc.m0w + mt * 16 + gq;
            size_t r1 = r0 + 8;
            float d0 = g_dinv[r0], d1 = g_dinv[r1];
#pragma unroll
            for (int nt = 0; nt < 8; nt++) {
                int c = wc.n0w + nt * 8 + tq * 2;
                float* a = acc[mt][nt];
                *(__half2*)(g_xwh + r0 * 128 + c) =
                    __floats2half2_rn(a[0] * d0, a[1] * d0);
                *(__half2*)(g_xwh + r1 * 128 + c) =
                    __floats2half2_rn(a[2] * d1, a[3] * d1);
            }
        }
        __syncthreads();   // all mma reads of A done before next tile's A build
    }
}

// ---------------------------------------------------------------------------
// Fused GEMM2+GEMM3 (persistent): h1 tile stays in smem.
// A-build reads fp16 conv. smem: AH|AL|W1H|W1L|W2H|W2L | b1 | b2 | W3 | red
// ---------------------------------------------------------------------------
#define OFF23_B1  (6 * BLOB_B)
#define OFF23_B2  (6 * BLOB_B + 512)
#define OFF23_W3  (6 * BLOB_B + 1024)
#define OFF23_RED (6 * BLOB_B + 1536)
#define SMEM23    (6 * BLOB_B + 2560)

__global__ __launch_bounds__(256)
void k_tc23(const float* __restrict__ nf, const float* __restrict__ act,
            const float* __restrict__ bg,
            const float* __restrict__ b1, const float* __restrict__ b2,
            const float* __restrict__ W3, const float* __restrict__ b3p,
            float* __restrict__ out)
{
    extern __shared__ char smem[];
    const uint32_t sb = smem_u32(smem);
    const int tid  = threadIdx.x;
    const int wid  = tid >> 5;
    const int lane = tid & 31;

    {   // W1 + W2 blobs + biases (once per SM)
        const uint4* w1h = &g_wblob[1][0][0];
        const uint4* w1l = &g_wblob[1][1][0];
        const uint4* w2h = &g_wblob[2][0][0];
        const uint4* w2l = &g_wblob[2][1][0];
        uint4* s1h = (uint4*)(smem + 2 * BLOB_B);
        uint4* s1l = (uint4*)(smem + 3 * BLOB_B);
        uint4* s2h = (uint4*)(smem + 4 * BLOB_B);
        uint4* s2l = (uint4*)(smem + 5 * BLOB_B);
        for (int i = tid; i < BLOB_B / 16; i += 256) {
            s1h[i] = w1h[i]; s1l[i] = w1l[i];
            s2h[i] = w2h[i]; s2l[i] = w2l[i];
        }
    }
    if (tid < 32)
        ((float4*)(smem + OFF23_B1))[tid] = ((const float4*)b1)[tid];
    else if (tid < 64)
        ((float4*)(smem + OFF23_B2))[tid - 32] = ((const float4*)b2)[tid - 32];
    else if (tid < 96)
        ((float4*)(smem + OFF23_W3))[tid - 64] = ((const float4*)W3)[tid - 64];

    const WarpCoords wc = warp_coords(wid, lane);
    const int gq = lane >> 2;
    const int tq = lane & 3;
    const float b3v = __ldg(b3p);

    for (int tile = blockIdx.x; tile < NTILE; tile += gridDim.x) {
        const size_t row0 = (size_t)tile * 128;
        {   // A = relu(conv+bg)+x   (conv fp16)
            int row  = tid >> 1;
            int half = tid & 1;
            size_t rowg = row0 + row;
            const float* srcx = half ? (act + rowg * 64) : (nf + rowg * 64);
            char* ah = smem + row * PITCH_B + half * 128;
            char* al = smem + BLOB_B + row * PITCH_B + half * 128;
#pragma unroll
            for (int q = 0; q < 16; q++) {
                int c0 = half * 64 + q * 4;
                float4 c4 = h4_to_f4(*(const uint2*)(g_convh + rowg * 128 + c0));
                float4 g4 = __ldg((const float4*)(bg + c0));
                float4 x4 = ((const float4*)srcx)[q];
                float v0 = fmaxf(c4.x + g4.x, 0.0f) + x4.x;
                float v1 = fmaxf(c4.y + g4.y, 0.0f) + x4.y;
                float v2 = fmaxf(c4.z + g4.z, 0.0f) + x4.z;
                float v3 = fmaxf(c4.w + g4.w, 0.0f) + x4.w;
                uint32_t h, l;
                split2(v0, v1, h, l);
                *(uint32_t*)(ah + q * 8) = h;  *(uint32_t*)(al + q * 8) = l;
                split2(v2, v3, h, l);
                *(uint32_t*)(ah + q * 8 + 4) = h;  *(uint32_t*)(al + q * 8 + 4) = l;
            }
        }
        __syncthreads();

        float acc[2][8][4];
#pragma unroll
        for (int mt = 0; mt < 2; mt++)
#pragma unroll
            for (int nt = 0; nt < 8; nt++)
#pragma unroll
                for (int q = 0; q < 4; q++) acc[mt][nt][q] = 0.0f;

        // ---- GEMM2: A @ W1 ----
        run_mma(acc, sb, sb + BLOB_B, sb + 2 * BLOB_B, sb + 3 * BLOB_B, wc);
        __syncthreads();

        // ---- h1 = lrelu(acc + b1) -> re-split into A blobs ----
        {
            const float* b1s = (const float*)(smem + OFF23_B1);
            char* ah = smem;
            char* al = smem + BLOB_B;
#pragma unroll
            for (int mt = 0; mt < 2; mt++) {
                int lr0 = wc.m0w + mt * 16 + gq;
                int lr1 = lr0 + 8;
#pragma unroll
                for (int nt = 0; nt < 8; nt++) {
                    int c = wc.n0w + nt * 8 + tq * 2;
                    float bb0 = b1s[c], bb1 = b1s[c + 1];
                    float* a = acc[mt][nt];
                    uint32_t h, l;
                    split2(lrelu(a[0] + bb0), lrelu(a[1] + bb1), h, l);
                    *(uint32_t*)(ah + lr0 * PITCH_B + c * 2) = h;
                    *(uint32_t*)(al + lr0 * PITCH_B + c * 2) = l;
                    split2(lrelu(a[2] + bb0), lrelu(a[3] + bb1), h, l);
                    *(uint32_t*)(ah + lr1 * PITCH_B + c * 2) = h;
                    *(uint32_t*)(al + lr1 * PITCH_B + c * 2) = l;
                }
            }
        }
        __syncthreads();

        // ---- GEMM3: h1 @ W2 ----
#pragma unroll
        for (int mt = 0; mt < 2; mt++)
#pragma unroll
            for (int nt = 0; nt < 8; nt++)
#pragma unroll
                for (int q = 0; q < 4; q++) acc[mt][nt][q] = 0.0f;
        run_mma(acc, sb, sb + BLOB_B, sb + 4 * BLOB_B, sb + 5 * BLOB_B, wc);

        // ---- head: out = lrelu(acc + b2) . W3 + b3 ----
        {
            const float* b2s = (const float*)(smem + OFF23_B2);
            const float* w3s = (const float*)(smem + OFF23_W3);
            float* red = (float*)(smem + OFF23_RED);   // [128][2]
#pragma unroll
            for (int mt = 0; mt < 2; mt++) {
                float s0 = 0.0f, s1 = 0.0f;
#pragma unroll
                for (int nt = 0; nt < 8; nt++) {
                    int c = wc.n0w + nt * 8 + tq * 2;
                    float bb0 = b2s[c], bb1 = b2s[c + 1];
                    float w0 = w3s[c],  w1 = w3s[c + 1];
                    float* a = acc[mt][nt];
                    s0 = fmaf(lrelu(a[0] + bb0), w0, s0);
                    s0 = fmaf(lrelu(a[1] + bb1), w1, s0);
                    s1 = fmaf(lrelu(a[2] + bb0), w0, s1);
                    s1 = fmaf(lrelu(a[3] + bb1), w1, s1);
                }
                s0 += __shfl_xor_sync(0xffffffffu, s0, 1);
                s0 += __shfl_xor_sync(0xffffffffu, s0, 2);
                s1 += __shfl_xor_sync(0xffffffffu, s1, 1);
                s1 += __shfl_xor_sync(0xffffffffu, s1, 2);
                if (tq == 0) {
                    int lr0 = wc.m0w + mt * 16 + gq;
                    red[lr0 * 2 + (wid & 1)]       = s0;
                    red[(lr0 + 8) * 2 + (wid & 1)] = s1;
                }
            }
            __syncthreads();   // also guards next tile's A-blob overwrite
            if (tid < 128)
                out[row0 + tid] = red[tid * 2] + red[tid * 2 + 1] + b3v;
        }
    }
}

// ---------------------------------------------------------------------------
extern "C" void kernel_launch(void* const* d_in, const int* in_sizes, int n_in,
                              void* d_out, int out_size)
{
    const float* nf  = (const float*)d_in[0];
    const float* act = (const float*)d_in[1];
    const int*   ei  = (const int*)d_in[2];     // JAX x64 disabled -> int32
    const float* Wg  = (const float*)d_in[3];
    const float* bg  = (const float*)d_in[4];
    const float* W1  = (const float*)d_in[5];
    const float* b1  = (const float*)d_in[6];
    const float* W2  = (const float*)d_in[7];
    const float* b2  = (const float*)d_in[8];
    const float* W3  = (const float*)d_in[9];
    const float* b3  = (const float*)d_in[10];
    float* out = (float*)d_out;

    cudaFuncSetAttribute(k_tc1,  cudaFuncAttributeMaxDynamicSharedMemorySize, SMEM1);
    cudaFuncSetAttribute(k_tc23, cudaFuncAttributeMaxDynamicSharedMemorySize, SMEM23);

    // Edge indexing structure (counting sort by dst) + weight prep
    k_init    <<<NBLK, 256>>>(Wg, W1, W2);
    k_degree  <<<(Bc * Ec + 255) / 256, 256>>>(ei);
    k_scanA   <<<NBLK, 256>>>();
    k_scanC   <<<NBLK, 256>>>();     // merged scanB+scanC
    k_reorder <<<(Bc * Ec + 255) / 256, 256>>>(ei);

    // GEMM1 (persistent): xwh = fp16((concat(nf,act) @ Wg) * dinv)
    k_tc1<<<NSM, 256, SMEM1>>>(nf, act);
    // conv (fp16) = dinv * (self + gather-sum)  [64 warps/SM, 2 LDG/warp/edge]
    k_aggregate<<<(MTOT * 32 + 255) / 256, 256>>>();
    // Fused GEMM2+GEMM3 (persistent, +head), fp16 conv input
    k_tc23<<<NSM, 256, SMEM23>>>(nf, act, bg, b1, b2, W3, b3, out);
}